// round 14
// baseline (speedup 1.0000x reference)
#include <cuda_runtime.h>
#include <cuda_bf16.h>

// ChordalPCWeightTransform: the two roll-permutations compose to identity on
// the data tensor; the op reduces to out[b,l,j] = softmax_j( x[b,l,j] * wrolled[l%144][j] )
// where wrolled[l][j] = w[(j - l/12 + 12) % 12] for j<12, w[12] for j==12.
//
// Pure HBM-streaming kernel: coalesced float4 staging through shared memory,
// per-thread 13-wide softmax (stride-13 smem access is bank-conflict-free).

#define RPB 256          // rows per block == threads per block
#define PC  13
#define NQ  12           // num_quality = 144/12
#define LBL 144

__global__ __launch_bounds__(RPB)
void chordal_softmax_kernel(const float* __restrict__ x,
                            const float* __restrict__ w,
                            float* __restrict__ out)
{
    __shared__ float s[RPB * PC];        // 3328 floats = 13312 B
    __shared__ float wtab[NQ * PC];      // 12 rolled weight vectors

    const int tid = threadIdx.x;
    const long long row0 = (long long)blockIdx.x * RPB;
    const long long base = row0 * PC;    // element offset; multiple of 3328 -> 16B aligned

    // Build the 12 rolled weight vectors (one per root pitch-class).
    if (tid < NQ * PC) {
        int r = tid / PC;
        int j = tid - r * PC;
        wtab[tid] = (j < NQ) ? w[(j - r + NQ) % NQ] : w[NQ];
    }

    // Coalesced load: 3328 floats = 832 float4 per block.
    const float4* __restrict__ src = reinterpret_cast<const float4*>(x + base);
    float4* s4 = reinterpret_cast<float4*>(s);
    const int N4 = RPB * PC / 4;  // 832
    #pragma unroll
    for (int i = tid; i < N4; i += RPB) s4[i] = src[i];
    __syncthreads();

    // Per-thread row softmax.
    {
        const long long row = row0 + tid;
        const int l = (int)(row % LBL);
        const int r = l / NQ;                 // root pitch class 0..11
        const float* __restrict__ wt = &wtab[r * PC];
        float* __restrict__ sr = &s[tid * PC];

        float v[PC];
        float m = -1e30f;
        #pragma unroll
        for (int j = 0; j < PC; ++j) {
            v[j] = sr[j] * wt[j];
            m = fmaxf(m, v[j]);
        }
        float sum = 0.0f;
        #pragma unroll
        for (int j = 0; j < PC; ++j) {
            v[j] = __expf(v[j] - m);
            sum += v[j];
        }
        const float inv = 1.0f / sum;
        #pragma unroll
        for (int j = 0; j < PC; ++j) sr[j] = v[j] * inv;
    }
    __syncthreads();

    // Coalesced store.
    float4* __restrict__ dst = reinterpret_cast<float4*>(out + base);
    #pragma unroll
    for (int i = tid; i < N4; i += RPB) dst[i] = s4[i];
}

extern "C" void kernel_launch(void* const* d_in, const int* in_sizes, int n_in,
                              void* d_out, int out_size)
{
    // metadata order: chordal_pc_vector [B,L,P] f32, scale_degree_weight [13] f32
    const float* x = (const float*)d_in[0];
    const float* w = (const float*)d_in[1];
    if (in_sizes[0] == PC) {  // defensive: swap if order reversed
        x = (const float*)d_in[1];
        w = (const float*)d_in[0];
    }
    float* out = (float*)d_out;

    const long long total = (long long)out_size;     // B*L*P = 122,683,392
    const long long rows  = total / PC;              // 9,437,184
    const int grid = (int)((rows + RPB - 1) / RPB);  // 36,864 (exact)

    chordal_softmax_kernel<<<grid, RPB>>>(x, w, out);
}